// round 1
// baseline (speedup 1.0000x reference)
#include <cuda_runtime.h>
#include <cstdint>

#define IN_F   768
#define HID    16
#define OUTF   21
#define NMAX   50000

// Scratch (no cudaMalloc allowed)
__device__ float g_xp  [NMAX * HID];
__device__ float g_agg1[NMAX * HID];
__device__ float g_agg2[NMAX * HID];

// ---------------- packed f32x2 helpers ----------------
__device__ __forceinline__ void ffma2(unsigned long long& acc,
                                      unsigned long long a,
                                      unsigned long long b) {
    asm("fma.rn.f32x2 %0, %1, %2, %3;" : "=l"(acc) : "l"(a), "l"(b), "l"(acc));
}
__device__ __forceinline__ float2 upk(unsigned long long v) {
    float2 r;
    asm("mov.b64 {%0, %1}, %2;" : "=f"(r.x), "=f"(r.y) : "l"(v));
    return r;
}
__device__ __forceinline__ void red4(float* p, float4 v) {
    asm volatile("red.global.add.v4.f32 [%0], {%1, %2, %3, %4};"
                 :: "l"(p), "f"(v.x), "f"(v.y), "f"(v.z), "f"(v.w) : "memory");
}

// ---------------- zero-init scratch ----------------
__global__ void k_zero(float4* a, float4* b, int n4) {
    int i = blockIdx.x * blockDim.x + threadIdx.x;
    if (i < n4) {
        a[i] = make_float4(0.f, 0.f, 0.f, 0.f);
        b[i] = make_float4(0.f, 0.f, 0.f, 0.f);
    }
}

// ---------------- K1: Xp = F @ W1  (50000x768 x 768x16) ----------------
// Block: 256 threads, tile 64 rows x 16 cols, k-tiled by 64.
// Thread (j = tid&15, ii = tid>>4) computes rows ii*4..ii*4+3, col j.
// Packed f32x2 FMAs: 1 LDS.128 (W) + 4 LDS.128 (F) + 8 FFMA2 per 4 k-steps.
#define BR  64
#define BK  64
#define LDF (BK + 4)   // 68-float row stride: 16B aligned, conflict-light

__global__ __launch_bounds__(256) void k_gemm1(
    const float* __restrict__ F, const float* __restrict__ W1,
    float* __restrict__ Xp, int nNodes)
{
    __shared__ float Fsh[BR * LDF];
    __shared__ float Wsh[HID * LDF];

    const int tid = threadIdx.x;
    const int j  = tid & 15;
    const int ii = tid >> 4;
    const int row0 = blockIdx.x * BR;

    unsigned long long accA[4] = {0ull, 0ull, 0ull, 0ull};
    unsigned long long accB[4] = {0ull, 0ull, 0ull, 0ull};

    for (int kt = 0; kt < IN_F; kt += BK) {
        // Stage feature tile: 64 rows x 64 floats, float4-coalesced
        #pragma unroll
        for (int t = 0; t < 4; t++) {
            int f  = tid + 256 * t;          // float4 index; 16 float4 per row
            int r  = f >> 4;
            int c4 = f & 15;
            float4 v = make_float4(0.f, 0.f, 0.f, 0.f);
            if (row0 + r < nNodes)
                v = *(const float4*)(F + (size_t)(row0 + r) * IN_F + kt + c4 * 4);
            *(float4*)(Fsh + r * LDF + c4 * 4) = v;
        }
        // Stage W1 tile transposed: Wsh[j][k_local]
        #pragma unroll
        for (int t = 0; t < 4; t++) {
            int idx = tid + 256 * t;          // 1024 floats
            int kl  = idx >> 4;
            int jj  = idx & 15;
            Wsh[jj * LDF + kl] = W1[(kt + kl) * HID + jj];
        }
        __syncthreads();

        #pragma unroll
        for (int k4 = 0; k4 < BK; k4 += 4) {
            ulonglong2 w = *(const ulonglong2*)(Wsh + j * LDF + k4);
            #pragma unroll
            for (int q = 0; q < 4; q++) {
                ulonglong2 fv = *(const ulonglong2*)(Fsh + (ii * 4 + q) * LDF + k4);
                ffma2(accA[q], fv.x, w.x);
                ffma2(accB[q], fv.y, w.y);
            }
        }
        __syncthreads();
    }

    #pragma unroll
    for (int q = 0; q < 4; q++) {
        float2 a = upk(accA[q]);
        float2 b = upk(accB[q]);
        float s = (a.x + a.y) + (b.x + b.y);
        int r = row0 + ii * 4 + q;
        if (r < nNodes) Xp[r * HID + j] = s;
    }
}

// ---------------- K2: agg1 += scatter(Xp[src] -> dst) ----------------
__global__ __launch_bounds__(256) void k_edge1(
    const float* __restrict__ xin, float* __restrict__ xout,
    const int* __restrict__ src, const int* __restrict__ dst, int nE)
{
    int e = blockIdx.x * blockDim.x + threadIdx.x;
    if (e >= nE) return;
    int s = src[e], d = dst[e];
    const float4* sp = (const float4*)(xin + (size_t)s * HID);
    float4 v0 = __ldg(sp + 0);
    float4 v1 = __ldg(sp + 1);
    float4 v2 = __ldg(sp + 2);
    float4 v3 = __ldg(sp + 3);
    float* op = xout + (size_t)d * HID;
    red4(op + 0,  v0);
    red4(op + 4,  v1);
    red4(op + 8,  v2);
    red4(op + 12, v3);
}

// ---------------- K4: agg2 += scatter(relu(agg1[src]+b1) -> dst) ----------------
__global__ __launch_bounds__(256) void k_edge2(
    const float* __restrict__ xin, float* __restrict__ xout,
    const int* __restrict__ src, const int* __restrict__ dst,
    const float* __restrict__ b1, int nE)
{
    int e = blockIdx.x * blockDim.x + threadIdx.x;
    if (e >= nE) return;
    int s = src[e], d = dst[e];
    const float4* sp = (const float4*)(xin + (size_t)s * HID);
    const float4* bp = (const float4*)b1;
    float* op = xout + (size_t)d * HID;
    #pragma unroll
    for (int c = 0; c < 4; c++) {
        float4 v = __ldg(sp + c);
        float4 b = __ldg(bp + c);
        v.x = fmaxf(v.x + b.x, 0.f);
        v.y = fmaxf(v.y + b.y, 0.f);
        v.z = fmaxf(v.z + b.z, 0.f);
        v.w = fmaxf(v.w + b.w, 0.f);
        red4(op + c * 4, v);
    }
}

// ---------------- K5: out = agg2 @ W2 + b2  (16 -> 21) ----------------
__global__ __launch_bounds__(256) void k_gemm2(
    const float* __restrict__ h, const float* __restrict__ W2,
    const float* __restrict__ b2, float* __restrict__ out, int nNodes)
{
    __shared__ float Ws[HID * OUTF];
    __shared__ float bs[OUTF];
    int tid = threadIdx.x;
    for (int i = tid; i < HID * OUTF; i += 256) Ws[i] = W2[i];
    if (tid < OUTF) bs[tid] = b2[tid];
    __syncthreads();

    int g = blockIdx.x * 256 + tid;              // over nNodes*OUTF
    if (g >= nNodes * OUTF) return;
    int row = g / OUTF;
    int col = g - row * OUTF;

    const float4* hr = (const float4*)(h + (size_t)row * HID);
    float4 h0 = __ldg(hr + 0), h1 = __ldg(hr + 1);
    float4 h2 = __ldg(hr + 2), h3 = __ldg(hr + 3);

    float acc = bs[col];
    acc = fmaf(h0.x, Ws[ 0 * OUTF + col], acc);
    acc = fmaf(h0.y, Ws[ 1 * OUTF + col], acc);
    acc = fmaf(h0.z, Ws[ 2 * OUTF + col], acc);
    acc = fmaf(h0.w, Ws[ 3 * OUTF + col], acc);
    acc = fmaf(h1.x, Ws[ 4 * OUTF + col], acc);
    acc = fmaf(h1.y, Ws[ 5 * OUTF + col], acc);
    acc = fmaf(h1.z, Ws[ 6 * OUTF + col], acc);
    acc = fmaf(h1.w, Ws[ 7 * OUTF + col], acc);
    acc = fmaf(h2.x, Ws[ 8 * OUTF + col], acc);
    acc = fmaf(h2.y, Ws[ 9 * OUTF + col], acc);
    acc = fmaf(h2.z, Ws[10 * OUTF + col], acc);
    acc = fmaf(h2.w, Ws[11 * OUTF + col], acc);
    acc = fmaf(h3.x, Ws[12 * OUTF + col], acc);
    acc = fmaf(h3.y, Ws[13 * OUTF + col], acc);
    acc = fmaf(h3.z, Ws[14 * OUTF + col], acc);
    acc = fmaf(h3.w, Ws[15 * OUTF + col], acc);
    out[g] = acc;
}

// ---------------- launch ----------------
extern "C" void kernel_launch(void* const* d_in, const int* in_sizes, int n_in,
                              void* d_out, int out_size)
{
    const float* feature = (const float*)d_in[0];
    const float* W1      = (const float*)d_in[1];
    const float* b1      = (const float*)d_in[2];
    const float* W2      = (const float*)d_in[3];
    const float* b2      = (const float*)d_in[4];
    const int*   src     = (const int*)  d_in[5];
    const int*   dst     = (const int*)  d_in[6];
    float*       out     = (float*)d_out;

    int nNodes = in_sizes[0] / IN_F;
    if (nNodes > NMAX) nNodes = NMAX;
    int nE = in_sizes[5];

    float *xp, *agg1, *agg2;
    cudaGetSymbolAddress((void**)&xp,   g_xp);
    cudaGetSymbolAddress((void**)&agg1, g_agg1);
    cudaGetSymbolAddress((void**)&agg2, g_agg2);

    int n4 = (nNodes * HID) / 4;
    k_zero<<<(n4 + 255) / 256, 256>>>((float4*)agg1, (float4*)agg2, n4);

    k_gemm1<<<(nNodes + BR - 1) / BR, 256>>>(feature, W1, xp, nNodes);

    k_edge1<<<(nE + 255) / 256, 256>>>(xp, agg1, src, dst, nE);

    k_edge2<<<(nE + 255) / 256, 256>>>(agg1, agg2, src, dst, b1, nE);

    k_gemm2<<<(nNodes * OUTF + 255) / 256, 256>>>(agg2, W2, b2, out, nNodes);
}